// round 3
// baseline (speedup 1.0000x reference)
#include <cuda_runtime.h>
#include <cuda_bf16.h>
#include <math.h>
#include <stdint.h>

// ---------------------------------------------------------------------------
// Problem constants
// ---------------------------------------------------------------------------
#define BATCH   2
#define CH      192
#define DIM     32
#define SPAT    (DIM*DIM*DIM)      // 32768
#define HID     768
#define KS      7
#define KV      343
#define NCELLS  1024               // 2 * 8*8*8
#define CELLTOK 64                 // 4*4*4

// ---------------------------------------------------------------------------
// Device scratch (static globals -- no runtime allocation)
// ---------------------------------------------------------------------------
__device__ int   g_cellList[NCELLS];
__device__ int   g_cellCount;
__device__ float g_yc[(size_t)NCELLS * CELLTOK * CH];    // compacted conv out

// ---------------------------------------------------------------------------
// Helpers
// ---------------------------------------------------------------------------
__device__ __forceinline__ float2 ffma2(float2 a, float2 b, float2 c) {
    union U { float2 f; unsigned long long u; };
    U A, B, C, D;
    A.f = a; B.f = b; C.f = c;
    asm("fma.rn.f32x2 %0, %1, %2, %3;" : "=l"(D.u) : "l"(A.u), "l"(B.u), "l"(C.u));
    return D.f;
}

__device__ __forceinline__ float tf32r(float x) {
    unsigned int u;
    asm("cvt.rna.tf32.f32 %0, %1;" : "=r"(u) : "f"(x));
    return __uint_as_float(u);
}

// mma.sync m16n8k8 tf32: d += a * b   (mapping verified by round-1 pass)
__device__ __forceinline__ void mma_tf32(float* d, const float* a, float b0, float b1) {
    asm volatile(
        "mma.sync.aligned.m16n8k8.row.col.f32.tf32.tf32.f32 "
        "{%0,%1,%2,%3}, {%4,%5,%6,%7}, {%8,%9}, {%0,%1,%2,%3};"
        : "+f"(d[0]), "+f"(d[1]), "+f"(d[2]), "+f"(d[3])
        : "r"(__float_as_uint(a[0])), "r"(__float_as_uint(a[1])),
          "r"(__float_as_uint(a[2])), "r"(__float_as_uint(a[3])),
          "r"(__float_as_uint(b0)),   "r"(__float_as_uint(b1)));
}

__device__ __forceinline__ float gelu_exact(float x) {
    return 0.5f * x * (1.0f + erff(x * 0.70710678118654752f));
}

__device__ __forceinline__ void cp_async16(void* smem_dst, const void* gmem_src) {
    unsigned s = (unsigned)__cvta_generic_to_shared(smem_dst);
    asm volatile("cp.async.cg.shared.global [%0], [%1], 16;\n" :: "r"(s), "l"(gmem_src));
}
#define CP_COMMIT() asm volatile("cp.async.commit_group;\n" ::: "memory")
#define CP_WAIT1()  asm volatile("cp.async.wait_group 1;\n" ::: "memory")

// ---------------------------------------------------------------------------
// Kernel 0: build compacted active-cell list (dtype-sniffing as before)
// ---------------------------------------------------------------------------
__global__ void build_cells_kernel(const void* __restrict__ maskp) {
    __shared__ int s_float, s_byte;
    __shared__ int wsum[32];
    int tid = threadIdx.x;
    if (tid == 0) { s_float = 0; s_byte = 0; }
    __syncthreads();
    if (tid < 256) {
        unsigned w = ((const unsigned*)maskp)[tid];
        if (w == 0x3F800000u) atomicOr(&s_float, 1);
        else if (w > 1u)      atomicOr(&s_byte, 1);
    }
    __syncthreads();
    int active;
    if (s_float)      active = (((const float*)maskp)[tid] != 0.0f) ? 1 : 0;
    else if (s_byte)  active = (((const unsigned char*)maskp)[tid] != 0) ? 1 : 0;
    else              active = (((const int*)maskp)[tid] != 0) ? 1 : 0;

    unsigned bal = __ballot_sync(0xffffffffu, active);
    int lane = tid & 31, wid = tid >> 5;
    int pre = __popc(bal & ((1u << lane) - 1u));
    if (lane == 31) wsum[wid] = pre + active;
    __syncthreads();
    if (wid == 0) {
        int v = wsum[lane];
        #pragma unroll
        for (int off = 1; off < 32; off <<= 1) {
            int t = __shfl_up_sync(0xffffffffu, v, off);
            if (lane >= off) v += t;
        }
        wsum[lane] = v;
    }
    __syncthreads();
    int base = (wid == 0) ? 0 : wsum[wid - 1];
    if (active) g_cellList[base + pre] = tid;
    if (tid == 1023) g_cellCount = wsum[31];
}

// ---------------------------------------------------------------------------
// Kernel 1: depthwise 7^3 conv on active cells (unchanged from round 1)
// ---------------------------------------------------------------------------
#define CONV_TILE_F2 1200
#define CONV_TILE_B  (8 * CONV_TILE_F2 * 8)
#define CONV_WGT_B   (8 * 344 * 8)
#define CONV_SOUT_B  (64 * 16 * 4)
#define CONV_SMEM    (CONV_TILE_B + CONV_WGT_B + CONV_SOUT_B)

__global__ __launch_bounds__(128)
void conv_kernel(const float* __restrict__ x,
                 const float* __restrict__ dw_w,
                 const float* __restrict__ dw_b) {
    int cellSlot = blockIdx.x / 12;
    if (cellSlot >= g_cellCount) return;
    int pg   = blockIdx.x % 12;
    int cell = g_cellList[cellSlot];
    int b  = cell >> 9;
    int cz = (cell >> 6) & 7, cy = (cell >> 3) & 7, cx = cell & 7;
    int z0 = cz * 4, y0 = cy * 4, x0 = cx * 4;
    int c0 = pg * 16;

    extern __shared__ char sm[];
    float2* tile = (float2*)sm;
    float2* wgt  = (float2*)(sm + CONV_TILE_B);
    float*  sOut = (float*)(sm + CONV_TILE_B + CONV_WGT_B);

    int tid = threadIdx.x;
    const float* xb = x + (size_t)b * CH * SPAT;

    for (int idx = tid; idx < 8 * 1000; idx += 128) {
        int p  = idx / 1000;
        int s  = idx - p * 1000;
        int zi = s / 100;
        int r  = s - zi * 100;
        int yi = r / 10;
        int xi = r - yi * 10;
        int gz = z0 + zi - 3, gy = y0 + yi - 3, gx = x0 + xi - 3;
        float v0 = 0.f, v1 = 0.f;
        if (gz >= 0 && gz < DIM && gy >= 0 && gy < DIM && gx >= 0 && gx < DIM) {
            size_t off = (size_t)(c0 + 2 * p) * SPAT + gz * 1024 + gy * 32 + gx;
            v0 = xb[off];
            v1 = xb[off + SPAT];
        }
        tile[p * CONV_TILE_F2 + (zi * 10 + yi) * 12 + xi] = make_float2(v0, v1);
    }
    for (int idx = tid; idx < 8 * KV; idx += 128) {
        int p = idx / KV;
        int t = idx - p * KV;
        wgt[p * 344 + t] = make_float2(dw_w[(c0 + 2 * p) * KV + t],
                                       dw_w[(c0 + 2 * p + 1) * KV + t]);
    }
    __syncthreads();

    int p  = tid >> 4;
    int z  = (tid >> 2) & 3;
    int yy = tid & 3;
    float2 bias = make_float2(dw_b[c0 + 2 * p], dw_b[c0 + 2 * p + 1]);
    float2 acc0 = bias, acc1 = bias, acc2 = bias, acc3 = bias;

    const float2* tp = tile + p * CONV_TILE_F2;
    const float2* wp = wgt + p * 344;

    for (int dz = 0; dz < 7; dz++) {
        for (int dy = 0; dy < 7; dy++) {
            const float2* row = tp + ((z + dz) * 10 + (yy + dy)) * 12;
            float4 q0 = *(const float4*)(row + 0);
            float4 q1 = *(const float4*)(row + 2);
            float4 q2 = *(const float4*)(row + 4);
            float4 q3 = *(const float4*)(row + 6);
            float4 q4 = *(const float4*)(row + 8);
            float2 rr[10];
            rr[0] = make_float2(q0.x, q0.y); rr[1] = make_float2(q0.z, q0.w);
            rr[2] = make_float2(q1.x, q1.y); rr[3] = make_float2(q1.z, q1.w);
            rr[4] = make_float2(q2.x, q2.y); rr[5] = make_float2(q2.z, q2.w);
            rr[6] = make_float2(q3.x, q3.y); rr[7] = make_float2(q3.z, q3.w);
            rr[8] = make_float2(q4.x, q4.y); rr[9] = make_float2(q4.z, q4.w);
            const float2* wr = wp + (dz * 7 + dy) * 7;
            #pragma unroll
            for (int dx = 0; dx < 7; dx++) {
                float2 w = wr[dx];
                acc0 = ffma2(rr[dx + 0], w, acc0);
                acc1 = ffma2(rr[dx + 1], w, acc1);
                acc2 = ffma2(rr[dx + 2], w, acc2);
                acc3 = ffma2(rr[dx + 3], w, acc3);
            }
        }
    }

    int widx = z * 16 + yy * 4;
    sOut[(widx + 0) * 16 + 2 * p] = acc0.x; sOut[(widx + 0) * 16 + 2 * p + 1] = acc0.y;
    sOut[(widx + 1) * 16 + 2 * p] = acc1.x; sOut[(widx + 1) * 16 + 2 * p + 1] = acc1.y;
    sOut[(widx + 2) * 16 + 2 * p] = acc2.x; sOut[(widx + 2) * 16 + 2 * p + 1] = acc2.y;
    sOut[(widx + 3) * 16 + 2 * p] = acc3.x; sOut[(widx + 3) * 16 + 2 * p + 1] = acc3.y;
    __syncthreads();

    float* yout = g_yc + (size_t)cellSlot * CELLTOK * CH + c0;
    #pragma unroll
    for (int k = 0; k < 8; k++) {
        int i  = k * 128 + tid;
        int w  = i >> 4;
        int ch = i & 15;
        yout[(size_t)w * CH + ch] = sOut[w * 16 + ch];
    }
}

// ---------------------------------------------------------------------------
// Kernel 2: FUSED LayerNorm + MLP (GEMM1 -> gelu -> GEMM2) per cell.
// 256 threads = 8 warps. GEMM2 accumulators (64x192) live in registers.
// cp.async double-overlap: W2(nc) loads under GEMM1, W1(nc+1) under GEMM2.
// smem: sY[64][196] | sW1[192][68] | sH[64][68] | sW2[64][196]  = 166 KB
// ---------------------------------------------------------------------------
#define SY_STR  196
#define SW1_STR 68
#define SH_STR  68
#define SW2_STR 196
#define OFF_W1  (64 * SY_STR)
#define OFF_H   (OFF_W1 + 192 * SW1_STR)
#define OFF_W2  (OFF_H + 64 * SH_STR)
#define FUSED_SMEM ((OFF_W2 + 64 * SW2_STR) * 4)

__global__ __launch_bounds__(256)
void mlp_fused_kernel(const float* __restrict__ ln_w, const float* __restrict__ ln_b,
                      const float* __restrict__ w1,   const float* __restrict__ bias1,
                      const float* __restrict__ w2,   const float* __restrict__ bias2,
                      const float* __restrict__ gamma, float* __restrict__ out) {
    int cellSlot = blockIdx.x;
    if (cellSlot >= g_cellCount) return;
    int cell = g_cellList[cellSlot];
    int b  = cell >> 9;
    int cz = (cell >> 6) & 7, cy = (cell >> 3) & 7, cx = cell & 7;
    int z0 = cz * 4, y0 = cy * 4, x0 = cx * 4;

    extern __shared__ float smf[];
    float* sY  = smf;
    float* sW1 = smf + OFF_W1;
    float* sH  = smf + OFF_H;
    float* sW2 = smf + OFF_W2;
    float* sO  = smf;                 // reuse sY region for output transpose

    int tid = threadIdx.x;

    // ---- prefetch W1(0) immediately (covered by y-load + LN) ----
    for (int i = tid; i < 3072; i += 256) {           // 192 rows x 16 vec4
        int k = i >> 4, q = i & 15;
        cp_async16(&sW1[k * SW1_STR + q * 4], w1 + (size_t)k * HID + q * 4);
    }
    CP_COMMIT();

    // ---- load y tile ----
    const float* yrow = g_yc + (size_t)cellSlot * CELLTOK * CH;
    for (int i = tid; i < 64 * 48; i += 256) {
        int r = i / 48, cq = i - r * 48;
        float4 v = *(const float4*)(yrow + (size_t)r * CH + cq * 4);
        *(float4*)&sY[r * SY_STR + cq * 4] = v;
    }
    __syncthreads();

    // ---- LayerNorm (4 threads per token row) + tf32 round ----
    {
        int row = tid >> 2, q = tid & 3;
        float* ar = &sY[row * SY_STR + q * 48];
        float s = 0.f, ss = 0.f;
        #pragma unroll
        for (int i = 0; i < 48; i++) { float v = ar[i]; s += v; ss += v * v; }
        s  += __shfl_xor_sync(0xffffffffu, s, 1);
        ss += __shfl_xor_sync(0xffffffffu, ss, 1);
        s  += __shfl_xor_sync(0xffffffffu, s, 2);
        ss += __shfl_xor_sync(0xffffffffu, ss, 2);
        float mu   = s * (1.0f / 192.0f);
        float var  = ss * (1.0f / 192.0f) - mu * mu;
        float rstd = rsqrtf(var + 1e-6f);
        #pragma unroll
        for (int i = 0; i < 48; i++) {
            int c = q * 48 + i;
            float v = (ar[i] - mu) * rstd * __ldg(ln_w + c) + __ldg(ln_b + c);
            ar[i] = tf32r(v);
        }
    }
    __syncthreads();

    int wid = tid >> 5, lane = tid & 31;
    int g = lane >> 2, tg = lane & 3;
    int m0  = (wid >> 1) * 16;        // M strip (4 strips of 16)
    int nh1 = (wid & 1) * 32;         // GEMM1 N half within 64-chunk
    int nh2 = (wid & 1) * 96;         // GEMM2 N half within 192

    float acc[12][4];
    #pragma unroll
    for (int s = 0; s < 12; s++)
        #pragma unroll
        for (int e = 0; e < 4; e++) acc[s][e] = 0.f;

    for (int nc = 0; nc < 12; nc++) {
        int n0 = nc * 64;

        // prefetch W2(nc) — consumed in Phase B below, covered by Phase A
        for (int i = tid; i < 3072; i += 256) {       // 64 rows x 48 vec4
            int k = i / 48, q = i - k * 48;
            cp_async16(&sW2[k * SW2_STR + q * 4], w2 + (size_t)(n0 + k) * CH + q * 4);
        }
        CP_COMMIT();
        CP_WAIT1();                    // W1(nc) ready (W2(nc) still in flight)
        __syncthreads();

        // ---- Phase A: GEMM1 chunk  c1 = sY(64x192) @ sW1(192x64) ----
        float c1[4][4];
        #pragma unroll
        for (int s = 0; s < 4; s++)
            #pragma unroll
            for (int e = 0; e < 4; e++) c1[s][e] = 0.f;

        for (int ks = 0; ks < 24; ks++) {
            int k0 = ks * 8;
            float av[4];
            av[0] = sY[(m0 + g) * SY_STR + k0 + tg];
            av[1] = sY[(m0 + g + 8) * SY_STR + k0 + tg];
            av[2] = sY[(m0 + g) * SY_STR + k0 + tg + 4];
            av[3] = sY[(m0 + g + 8) * SY_STR + k0 + tg + 4];
            #pragma unroll
            for (int sub = 0; sub < 4; sub++) {
                float bb0 = sW1[(k0 + tg) * SW1_STR + nh1 + sub * 8 + g];
                float bb1 = sW1[(k0 + tg + 4) * SW1_STR + nh1 + sub * 8 + g];
                mma_tf32(c1[sub], av, bb0, bb1);
            }
        }

        // ---- epilogue: +b1, gelu, tf32 -> sH  (sH free: barrier after B) ----
        #pragma unroll
        for (int sub = 0; sub < 4; sub++) {
            int nl = nh1 + sub * 8 + 2 * tg;
            float bb0 = __ldg(bias1 + n0 + nl), bb1 = __ldg(bias1 + n0 + nl + 1);
            sH[(m0 + g) * SH_STR + nl]         = tf32r(gelu_exact(c1[sub][0] + bb0));
            sH[(m0 + g) * SH_STR + nl + 1]     = tf32r(gelu_exact(c1[sub][1] + bb1));
            sH[(m0 + g + 8) * SH_STR + nl]     = tf32r(gelu_exact(c1[sub][2] + bb0));
            sH[(m0 + g + 8) * SH_STR + nl + 1] = tf32r(gelu_exact(c1[sub][3] + bb1));
        }
        __syncthreads();               // sH visible; sW1 fully consumed

        // prefetch W1(nc+1) — covered by Phase B
        if (nc + 1 < 12) {
            int n1 = (nc + 1) * 64;
            for (int i = tid; i < 3072; i += 256) {
                int k = i >> 4, q = i & 15;
                cp_async16(&sW1[k * SW1_STR + q * 4], w1 + (size_t)k * HID + n1 + q * 4);
            }
        }
        CP_COMMIT();                   // (empty group on last iter is legal)
        CP_WAIT1();                    // W2(nc) ready (W1(nc+1) in flight)
        __syncthreads();

        // ---- Phase B: GEMM2 partial  acc += sH(64x64) @ sW2(64x192) ----
        for (int ks = 0; ks < 8; ks++) {
            int k0 = ks * 8;
            float av[4];
            av[0] = sH[(m0 + g) * SH_STR + k0 + tg];
            av[1] = sH[(m0 + g + 8) * SH_STR + k0 + tg];
            av[2] = sH[(m0 + g) * SH_STR + k0 + tg + 4];
            av[3] = sH[(m0 + g + 8) * SH_STR + k0 + tg + 4];
            #pragma unroll
            for (int sub = 0; sub < 12; sub++) {
                float bb0 = sW2[(k0 + tg) * SW2_STR + nh2 + sub * 8 + g];
                float bb1 = sW2[(k0 + tg + 4) * SW2_STR + nh2 + sub * 8 + g];
                mma_tf32(acc[sub], av, bb0, bb1);
            }
        }
        __syncthreads();               // sH / sW2 free for next nc
    }

    // ---- final epilogue: +b2, *gamma -> sO (token-major) ----
    #pragma unroll
    for (int sub = 0; sub < 12; sub++) {
        int n = nh2 + sub * 8 + 2 * tg;
        float g0 = __ldg(gamma + n), g1 = __ldg(gamma + n + 1);
        float bb0 = __ldg(bias2 + n), bb1 = __ldg(bias2 + n + 1);
        sO[(m0 + g) * SY_STR + n]         = g0 * (acc[sub][0] + bb0);
        sO[(m0 + g) * SY_STR + n + 1]     = g1 * (acc[sub][1] + bb1);
        sO[(m0 + g + 8) * SY_STR + n]     = g0 * (acc[sub][2] + bb0);
        sO[(m0 + g + 8) * SY_STR + n + 1] = g1 * (acc[sub][3] + bb1);
    }
    __syncthreads();

    // ---- coalesced scatter: per (c, z, y) write float4 along x ----
    for (int i = tid; i < 3072; i += 256) {
        int c = i >> 4, r = i & 15;
        int z = r >> 2, y = r & 3;
        int tok = z * 16 + y * 4;
        float4 v;
        v.x = sO[(tok + 0) * SY_STR + c];
        v.y = sO[(tok + 1) * SY_STR + c];
        v.z = sO[(tok + 2) * SY_STR + c];
        v.w = sO[(tok + 3) * SY_STR + c];
        size_t off = ((size_t)(b * CH + c)) * SPAT + (size_t)(z0 + z) * 1024
                   + (size_t)(y0 + y) * 32 + x0;
        *(float4*)(out + off) = v;
    }
}

// ---------------------------------------------------------------------------
// Launch
// ---------------------------------------------------------------------------
extern "C" void kernel_launch(void* const* d_in, const int* in_sizes, int n_in,
                              void* d_out, int out_size) {
    const float* x     = (const float*)d_in[0];
    const void*  mask  = d_in[1];
    const float* dw_w  = (const float*)d_in[2];
    const float* dw_b  = (const float*)d_in[3];
    const float* ln_w  = (const float*)d_in[4];
    const float* ln_b  = (const float*)d_in[5];
    const float* w1    = (const float*)d_in[6];
    const float* b1    = (const float*)d_in[7];
    const float* w2    = (const float*)d_in[8];
    const float* b2    = (const float*)d_in[9];
    const float* gamma = (const float*)d_in[10];
    float* out = (float*)d_out;

    cudaFuncSetAttribute(conv_kernel, cudaFuncAttributeMaxDynamicSharedMemorySize, CONV_SMEM);
    cudaFuncSetAttribute(mlp_fused_kernel, cudaFuncAttributeMaxDynamicSharedMemorySize, FUSED_SMEM);

    cudaMemsetAsync(d_out, 0, (size_t)out_size * sizeof(float));
    build_cells_kernel<<<1, 1024>>>(mask);
    conv_kernel<<<NCELLS * 12, 128, CONV_SMEM>>>(x, dw_w, dw_b);
    mlp_fused_kernel<<<NCELLS, 256, FUSED_SMEM>>>(ln_w, ln_b, w1, b1, w2, b2, gamma, out);
}

// round 4
// speedup vs baseline: 1.6648x; 1.6648x over previous
#include <cuda_runtime.h>
#include <cuda_bf16.h>
#include <math.h>
#include <stdint.h>

// ---------------------------------------------------------------------------
// Problem constants
// ---------------------------------------------------------------------------
#define BATCH   2
#define CH      192
#define DIM     32
#define SPAT    (DIM*DIM*DIM)      // 32768
#define HID     768
#define KS      7
#define KV      343
#define NCELLS  1024               // 2 * 8*8*8
#define CELLTOK 64                 // 4*4*4

// ---------------------------------------------------------------------------
// Device scratch (static globals -- no runtime allocation)
// ---------------------------------------------------------------------------
__device__ int   g_cellList[NCELLS];
__device__ int   g_cellCount;
__device__ float g_yc[(size_t)NCELLS * CELLTOK * CH];    // compacted conv out
__device__ float g_h [(size_t)NCELLS * CELLTOK * HID];   // hidden activations

// ---------------------------------------------------------------------------
// Helpers
// ---------------------------------------------------------------------------
__device__ __forceinline__ float2 ffma2(float2 a, float2 b, float2 c) {
    union U { float2 f; unsigned long long u; };
    U A, B, C, D;
    A.f = a; B.f = b; C.f = c;
    asm("fma.rn.f32x2 %0, %1, %2, %3;" : "=l"(D.u) : "l"(A.u), "l"(B.u), "l"(C.u));
    return D.f;
}

__device__ __forceinline__ float tf32r(float x) {
    unsigned int u;
    asm("cvt.rna.tf32.f32 %0, %1;" : "=r"(u) : "f"(x));
    return __uint_as_float(u);
}

// mma.sync m16n8k8 tf32: d += a * b   (mapping verified by round-1 pass)
__device__ __forceinline__ void mma_tf32(float* d, const float* a, float b0, float b1) {
    asm volatile(
        "mma.sync.aligned.m16n8k8.row.col.f32.tf32.tf32.f32 "
        "{%0,%1,%2,%3}, {%4,%5,%6,%7}, {%8,%9}, {%0,%1,%2,%3};"
        : "+f"(d[0]), "+f"(d[1]), "+f"(d[2]), "+f"(d[3])
        : "r"(__float_as_uint(a[0])), "r"(__float_as_uint(a[1])),
          "r"(__float_as_uint(a[2])), "r"(__float_as_uint(a[3])),
          "r"(__float_as_uint(b0)),   "r"(__float_as_uint(b1)));
}

__device__ __forceinline__ float gelu_exact(float x) {
    return 0.5f * x * (1.0f + erff(x * 0.70710678118654752f));
}

__device__ __forceinline__ void cp_async16(void* smem_dst, const void* gmem_src) {
    unsigned s = (unsigned)__cvta_generic_to_shared(smem_dst);
    asm volatile("cp.async.cg.shared.global [%0], [%1], 16;\n" :: "r"(s), "l"(gmem_src));
}
#define CP_COMMIT() asm volatile("cp.async.commit_group;\n" ::: "memory")
#define CP_WAIT1()  asm volatile("cp.async.wait_group 1;\n" ::: "memory")

// ---------------------------------------------------------------------------
// Kernel 0: build compacted active-cell list (dtype-sniffing)
// ---------------------------------------------------------------------------
__global__ void build_cells_kernel(const void* __restrict__ maskp) {
    __shared__ int s_float, s_byte;
    __shared__ int wsum[32];
    int tid = threadIdx.x;
    if (tid == 0) { s_float = 0; s_byte = 0; }
    __syncthreads();
    if (tid < 256) {
        unsigned w = ((const unsigned*)maskp)[tid];
        if (w == 0x3F800000u) atomicOr(&s_float, 1);
        else if (w > 1u)      atomicOr(&s_byte, 1);
    }
    __syncthreads();
    int active;
    if (s_float)      active = (((const float*)maskp)[tid] != 0.0f) ? 1 : 0;
    else if (s_byte)  active = (((const unsigned char*)maskp)[tid] != 0) ? 1 : 0;
    else              active = (((const int*)maskp)[tid] != 0) ? 1 : 0;

    unsigned bal = __ballot_sync(0xffffffffu, active);
    int lane = tid & 31, wid = tid >> 5;
    int pre = __popc(bal & ((1u << lane) - 1u));
    if (lane == 31) wsum[wid] = pre + active;
    __syncthreads();
    if (wid == 0) {
        int v = wsum[lane];
        #pragma unroll
        for (int off = 1; off < 32; off <<= 1) {
            int t = __shfl_up_sync(0xffffffffu, v, off);
            if (lane >= off) v += t;
        }
        wsum[lane] = v;
    }
    __syncthreads();
    int base = (wid == 0) ? 0 : wsum[wid - 1];
    if (active) g_cellList[base + pre] = tid;
    if (tid == 1023) g_cellCount = wsum[31];
}

// ---------------------------------------------------------------------------
// Kernel 1: depthwise 7^3 conv on active cells (unchanged from round 1)
// ---------------------------------------------------------------------------
#define CONV_TILE_F2 1200
#define CONV_TILE_B  (8 * CONV_TILE_F2 * 8)
#define CONV_WGT_B   (8 * 344 * 8)
#define CONV_SOUT_B  (64 * 16 * 4)
#define CONV_SMEM    (CONV_TILE_B + CONV_WGT_B + CONV_SOUT_B)

__global__ __launch_bounds__(128)
void conv_kernel(const float* __restrict__ x,
                 const float* __restrict__ dw_w,
                 const float* __restrict__ dw_b) {
    int cellSlot = blockIdx.x / 12;
    if (cellSlot >= g_cellCount) return;
    int pg   = blockIdx.x % 12;
    int cell = g_cellList[cellSlot];
    int b  = cell >> 9;
    int cz = (cell >> 6) & 7, cy = (cell >> 3) & 7, cx = cell & 7;
    int z0 = cz * 4, y0 = cy * 4, x0 = cx * 4;
    int c0 = pg * 16;

    extern __shared__ char sm[];
    float2* tile = (float2*)sm;
    float2* wgt  = (float2*)(sm + CONV_TILE_B);
    float*  sOut = (float*)(sm + CONV_TILE_B + CONV_WGT_B);

    int tid = threadIdx.x;
    const float* xb = x + (size_t)b * CH * SPAT;

    for (int idx = tid; idx < 8 * 1000; idx += 128) {
        int p  = idx / 1000;
        int s  = idx - p * 1000;
        int zi = s / 100;
        int r  = s - zi * 100;
        int yi = r / 10;
        int xi = r - yi * 10;
        int gz = z0 + zi - 3, gy = y0 + yi - 3, gx = x0 + xi - 3;
        float v0 = 0.f, v1 = 0.f;
        if (gz >= 0 && gz < DIM && gy >= 0 && gy < DIM && gx >= 0 && gx < DIM) {
            size_t off = (size_t)(c0 + 2 * p) * SPAT + gz * 1024 + gy * 32 + gx;
            v0 = xb[off];
            v1 = xb[off + SPAT];
        }
        tile[p * CONV_TILE_F2 + (zi * 10 + yi) * 12 + xi] = make_float2(v0, v1);
    }
    for (int idx = tid; idx < 8 * KV; idx += 128) {
        int p = idx / KV;
        int t = idx - p * KV;
        wgt[p * 344 + t] = make_float2(dw_w[(c0 + 2 * p) * KV + t],
                                       dw_w[(c0 + 2 * p + 1) * KV + t]);
    }
    __syncthreads();

    int p  = tid >> 4;
    int z  = (tid >> 2) & 3;
    int yy = tid & 3;
    float2 bias = make_float2(dw_b[c0 + 2 * p], dw_b[c0 + 2 * p + 1]);
    float2 acc0 = bias, acc1 = bias, acc2 = bias, acc3 = bias;

    const float2* tp = tile + p * CONV_TILE_F2;
    const float2* wp = wgt + p * 344;

    for (int dz = 0; dz < 7; dz++) {
        for (int dy = 0; dy < 7; dy++) {
            const float2* row = tp + ((z + dz) * 10 + (yy + dy)) * 12;
            float4 q0 = *(const float4*)(row + 0);
            float4 q1 = *(const float4*)(row + 2);
            float4 q2 = *(const float4*)(row + 4);
            float4 q3 = *(const float4*)(row + 6);
            float4 q4 = *(const float4*)(row + 8);
            float2 rr[10];
            rr[0] = make_float2(q0.x, q0.y); rr[1] = make_float2(q0.z, q0.w);
            rr[2] = make_float2(q1.x, q1.y); rr[3] = make_float2(q1.z, q1.w);
            rr[4] = make_float2(q2.x, q2.y); rr[5] = make_float2(q2.z, q2.w);
            rr[6] = make_float2(q3.x, q3.y); rr[7] = make_float2(q3.z, q3.w);
            rr[8] = make_float2(q4.x, q4.y); rr[9] = make_float2(q4.z, q4.w);
            const float2* wr = wp + (dz * 7 + dy) * 7;
            #pragma unroll
            for (int dx = 0; dx < 7; dx++) {
                float2 w = wr[dx];
                acc0 = ffma2(rr[dx + 0], w, acc0);
                acc1 = ffma2(rr[dx + 1], w, acc1);
                acc2 = ffma2(rr[dx + 2], w, acc2);
                acc3 = ffma2(rr[dx + 3], w, acc3);
            }
        }
    }

    int widx = z * 16 + yy * 4;
    sOut[(widx + 0) * 16 + 2 * p] = acc0.x; sOut[(widx + 0) * 16 + 2 * p + 1] = acc0.y;
    sOut[(widx + 1) * 16 + 2 * p] = acc1.x; sOut[(widx + 1) * 16 + 2 * p + 1] = acc1.y;
    sOut[(widx + 2) * 16 + 2 * p] = acc2.x; sOut[(widx + 2) * 16 + 2 * p + 1] = acc2.y;
    sOut[(widx + 3) * 16 + 2 * p] = acc3.x; sOut[(widx + 3) * 16 + 2 * p + 1] = acc3.y;
    __syncthreads();

    float* yout = g_yc + (size_t)cellSlot * CELLTOK * CH + c0;
    #pragma unroll
    for (int k = 0; k < 8; k++) {
        int i  = k * 128 + tid;
        int w  = i >> 4;
        int ch = i & 15;
        yout[(size_t)w * CH + ch] = sOut[w * 16 + ch];
    }
}

// ---------------------------------------------------------------------------
// Kernel 2: LayerNorm + GEMM1 + gelu -> g_h.
// N chunks of 32, double-buffered W1 via cp.async. 256 thr = 8 warps (4Mx2N).
// smem: sY[64][196] + sW1[2][192][40]  = 111,616 B  (2 blocks/SM)
// Strides: 196 % 32 == 4 (A loads 4g+tg conflict-free),
//          40  % 32 == 8 (B loads 8tg+g conflict-free).
// ---------------------------------------------------------------------------
#define SY1   196
#define SWB1  40
#define M1_OFF_W1 (64 * SY1)
#define M1_SMEM ((M1_OFF_W1 + 2 * 192 * SWB1) * 4)

__global__ __launch_bounds__(256)
void mlp1_kernel(const float* __restrict__ ln_w, const float* __restrict__ ln_b,
                 const float* __restrict__ w1,   const float* __restrict__ bias1) {
    int cellSlot = blockIdx.x;
    if (cellSlot >= g_cellCount) return;

    extern __shared__ float sm1[];
    float* sY = sm1;
    float* sW = sm1 + M1_OFF_W1;      // two buffers of 192*40

    int tid = threadIdx.x;

    // prefetch W1 chunk 0 into buf 0 (covered by y-load + LN)
    {
        for (int i = tid; i < 1536; i += 256) {   // 192 rows x 8 vec4
            int k = i >> 3, q = i & 7;
            cp_async16(&sW[k * SWB1 + q * 4], w1 + (size_t)k * HID + q * 4);
        }
        CP_COMMIT();
    }

    // load y tile
    const float* yrow = g_yc + (size_t)cellSlot * CELLTOK * CH;
    for (int i = tid; i < 64 * 48; i += 256) {
        int r = i / 48, cq = i - r * 48;
        float4 v = *(const float4*)(yrow + (size_t)r * CH + cq * 4);
        *(float4*)&sY[r * SY1 + cq * 4] = v;
    }
    __syncthreads();

    // LayerNorm (4 threads per token row) + tf32 round in place
    {
        int row = tid >> 2, q = tid & 3;
        float* ar = &sY[row * SY1 + q * 48];
        float s = 0.f, ss = 0.f;
        #pragma unroll
        for (int i = 0; i < 48; i++) { float v = ar[i]; s += v; ss += v * v; }
        s  += __shfl_xor_sync(0xffffffffu, s, 1);
        ss += __shfl_xor_sync(0xffffffffu, ss, 1);
        s  += __shfl_xor_sync(0xffffffffu, s, 2);
        ss += __shfl_xor_sync(0xffffffffu, ss, 2);
        float mu   = s * (1.0f / 192.0f);
        float var  = ss * (1.0f / 192.0f) - mu * mu;
        float rstd = rsqrtf(var + 1e-6f);
        #pragma unroll
        for (int i = 0; i < 48; i++) {
            int c = q * 48 + i;
            float v = (ar[i] - mu) * rstd * __ldg(ln_w + c) + __ldg(ln_b + c);
            ar[i] = tf32r(v);
        }
    }

    int wid = tid >> 5, lane = tid & 31;
    int g = lane >> 2, tg = lane & 3;
    int m0  = (wid >> 1) * 16;
    int nh1 = (wid & 1) * 16;
    float* hout = g_h + (size_t)cellSlot * CELLTOK * HID;

    for (int nc = 0; nc < 24; nc++) {
        // prefetch next chunk into other buffer (empty group on last iter)
        if (nc + 1 < 24) {
            float* dst = sW + ((nc + 1) & 1) * 192 * SWB1;
            int n1 = (nc + 1) * 32;
            for (int i = tid; i < 1536; i += 256) {
                int k = i >> 3, q = i & 7;
                cp_async16(&dst[k * SWB1 + q * 4], w1 + (size_t)k * HID + n1 + q * 4);
            }
        }
        CP_COMMIT();
        CP_WAIT1();                       // chunk nc resident
        __syncthreads();

        const float* sB = sW + (nc & 1) * 192 * SWB1;
        float c1[2][4];
        #pragma unroll
        for (int s = 0; s < 2; s++)
            #pragma unroll
            for (int e = 0; e < 4; e++) c1[s][e] = 0.f;

        #pragma unroll 4
        for (int ks = 0; ks < 24; ks++) {
            int k0 = ks * 8;
            float av[4];
            av[0] = sY[(m0 + g) * SY1 + k0 + tg];
            av[1] = sY[(m0 + g + 8) * SY1 + k0 + tg];
            av[2] = sY[(m0 + g) * SY1 + k0 + tg + 4];
            av[3] = sY[(m0 + g + 8) * SY1 + k0 + tg + 4];
            #pragma unroll
            for (int sub = 0; sub < 2; sub++) {
                float bb0 = sB[(k0 + tg) * SWB1 + nh1 + sub * 8 + g];
                float bb1 = sB[(k0 + tg + 4) * SWB1 + nh1 + sub * 8 + g];
                mma_tf32(c1[sub], av, bb0, bb1);
            }
        }

        // epilogue: +b1, gelu, tf32 -> g_h (float2 stores)
        int n0 = nc * 32;
        #pragma unroll
        for (int sub = 0; sub < 2; sub++) {
            int n = n0 + nh1 + sub * 8 + 2 * tg;
            float bb0 = __ldg(bias1 + n), bb1 = __ldg(bias1 + n + 1);
            float2 v0 = make_float2(tf32r(gelu_exact(c1[sub][0] + bb0)),
                                    tf32r(gelu_exact(c1[sub][1] + bb1)));
            float2 v1 = make_float2(tf32r(gelu_exact(c1[sub][2] + bb0)),
                                    tf32r(gelu_exact(c1[sub][3] + bb1)));
            *(float2*)&hout[(size_t)(m0 + g) * HID + n]     = v0;
            *(float2*)&hout[(size_t)(m0 + g + 8) * HID + n] = v1;
        }
        __syncthreads();                  // all reads of buf done before overwrite
    }
}

// ---------------------------------------------------------------------------
// Kernel 3: GEMM2 + b2 + gamma -> dense NCDHW scatter.
// K chunks of 32, double-buffered H and W2 via cp.async. 256 thr (4Mx2N).
// smem: sA[2][64][36] + sB[2][32][200] = 69,632 B (3 blocks/SM)
// sO stride 197 overlays sB region for output transpose.
// ---------------------------------------------------------------------------
#define SA2   36
#define SB2   200
#define SO2   197
#define M2_OFF_B (2 * 64 * SA2)
#define M2_SMEM ((M2_OFF_B + 2 * 32 * SB2) * 4)

__global__ __launch_bounds__(256)
void mlp2_kernel(const float* __restrict__ w2, const float* __restrict__ bias2,
                 const float* __restrict__ gamma, float* __restrict__ out) {
    int cellSlot = blockIdx.x;
    if (cellSlot >= g_cellCount) return;
    int cell = g_cellList[cellSlot];
    int b  = cell >> 9;
    int cz = (cell >> 6) & 7, cy = (cell >> 3) & 7, cx = cell & 7;
    int z0 = cz * 4, y0 = cy * 4, x0 = cx * 4;

    extern __shared__ float sm2[];
    float* sAb = sm2;                  // two buffers of 64*36
    float* sBb = sm2 + M2_OFF_B;       // two buffers of 32*200
    float* sO  = sm2 + M2_OFF_B;       // overlay (after compute completes)

    int tid = threadIdx.x;
    const float* hrow = g_h + (size_t)cellSlot * CELLTOK * HID;

    // prefetch chunk 0
    {
        for (int i = tid; i < 512; i += 256) {        // H: 64 x 8 vec4
            int r = i >> 3, kq = i & 7;
            cp_async16(&sAb[r * SA2 + kq * 4], hrow + (size_t)r * HID + kq * 4);
        }
        for (int i = tid; i < 1536; i += 256) {       // W2: 32 x 48 vec4
            int k = i / 48, q = i - k * 48;
            cp_async16(&sBb[k * SB2 + q * 4], w2 + (size_t)k * CH + q * 4);
        }
        CP_COMMIT();
    }

    int wid = tid >> 5, lane = tid & 31;
    int g = lane >> 2, tg = lane & 3;
    int m0  = (wid >> 1) * 16;
    int nh2 = (wid & 1) * 96;

    float acc[12][4];
    #pragma unroll
    for (int s = 0; s < 12; s++)
        #pragma unroll
        for (int e = 0; e < 4; e++) acc[s][e] = 0.f;

    for (int kc = 0; kc < 24; kc++) {
        if (kc + 1 < 24) {
            int kb = (kc + 1) * 32;
            float* dA = sAb + ((kc + 1) & 1) * 64 * SA2;
            float* dB = sBb + ((kc + 1) & 1) * 32 * SB2;
            for (int i = tid; i < 512; i += 256) {
                int r = i >> 3, kq = i & 7;
                cp_async16(&dA[r * SA2 + kq * 4], hrow + (size_t)r * HID + kb + kq * 4);
            }
            for (int i = tid; i < 1536; i += 256) {
                int k = i / 48, q = i - k * 48;
                cp_async16(&dB[k * SB2 + q * 4], w2 + (size_t)(kb + k) * CH + q * 4);
            }
        }
        CP_COMMIT();
        CP_WAIT1();
        __syncthreads();

        const float* sA = sAb + (kc & 1) * 64 * SA2;
        const float* sB = sBb + (kc & 1) * 32 * SB2;

        #pragma unroll
        for (int ks = 0; ks < 4; ks++) {
            int k0 = ks * 8;
            float av[4];
            av[0] = sA[(m0 + g) * SA2 + k0 + tg];
            av[1] = sA[(m0 + g + 8) * SA2 + k0 + tg];
            av[2] = sA[(m0 + g) * SA2 + k0 + tg + 4];
            av[3] = sA[(m0 + g + 8) * SA2 + k0 + tg + 4];
            #pragma unroll
            for (int sub = 0; sub < 12; sub++) {
                float bb0 = sB[(k0 + tg) * SB2 + nh2 + sub * 8 + g];
                float bb1 = sB[(k0 + tg + 4) * SB2 + nh2 + sub * 8 + g];
                mma_tf32(acc[sub], av, bb0, bb1);
            }
        }
        __syncthreads();                  // buf reads done before overwrite
    }

    // epilogue: +b2, *gamma -> sO (token-major, stride 197)
    #pragma unroll
    for (int sub = 0; sub < 12; sub++) {
        int n = nh2 + sub * 8 + 2 * tg;
        float g0 = __ldg(gamma + n), g1 = __ldg(gamma + n + 1);
        float bb0 = __ldg(bias2 + n), bb1 = __ldg(bias2 + n + 1);
        sO[(m0 + g) * SO2 + n]         = g0 * (acc[sub][0] + bb0);
        sO[(m0 + g) * SO2 + n + 1]     = g1 * (acc[sub][1] + bb1);
        sO[(m0 + g + 8) * SO2 + n]     = g0 * (acc[sub][2] + bb0);
        sO[(m0 + g + 8) * SO2 + n + 1] = g1 * (acc[sub][3] + bb1);
    }
    __syncthreads();

    // coalesced scatter: per (c, z, y) write float4 along x
    for (int i = tid; i < 3072; i += 256) {
        int c = i >> 4, r = i & 15;
        int z = r >> 2, y = r & 3;
        int tok = z * 16 + y * 4;
        float4 v;
        v.x = sO[(tok + 0) * SO2 + c];
        v.y = sO[(tok + 1) * SO2 + c];
        v.z = sO[(tok + 2) * SO2 + c];
        v.w = sO[(tok + 3) * SO2 + c];
        size_t off = ((size_t)(b * CH + c)) * SPAT + (size_t)(z0 + z) * 1024
                   + (size_t)(y0 + y) * 32 + x0;
        *(float4*)(out + off) = v;
    }
}

// ---------------------------------------------------------------------------
// Launch
// ---------------------------------------------------------------------------
extern "C" void kernel_launch(void* const* d_in, const int* in_sizes, int n_in,
                              void* d_out, int out_size) {
    const float* x     = (const float*)d_in[0];
    const void*  mask  = d_in[1];
    const float* dw_w  = (const float*)d_in[2];
    const float* dw_b  = (const float*)d_in[3];
    const float* ln_w  = (const float*)d_in[4];
    const float* ln_b  = (const float*)d_in[5];
    const float* w1    = (const float*)d_in[6];
    const float* b1    = (const float*)d_in[7];
    const float* w2    = (const float*)d_in[8];
    const float* b2    = (const float*)d_in[9];
    const float* gamma = (const float*)d_in[10];
    float* out = (float*)d_out;

    cudaFuncSetAttribute(conv_kernel, cudaFuncAttributeMaxDynamicSharedMemorySize, CONV_SMEM);
    cudaFuncSetAttribute(mlp1_kernel, cudaFuncAttributeMaxDynamicSharedMemorySize, M1_SMEM);
    cudaFuncSetAttribute(mlp2_kernel, cudaFuncAttributeMaxDynamicSharedMemorySize, M2_SMEM);

    cudaMemsetAsync(d_out, 0, (size_t)out_size * sizeof(float));
    build_cells_kernel<<<1, 1024>>>(mask);
    conv_kernel<<<NCELLS * 12, 128, CONV_SMEM>>>(x, dw_w, dw_b);
    mlp1_kernel<<<NCELLS, 256, M1_SMEM>>>(ln_w, ln_b, w1, b1);
    mlp2_kernel<<<NCELLS, 256, M2_SMEM>>>(w2, b2, gamma, out);
}